// round 3
// baseline (speedup 1.0000x reference)
#include <cuda_runtime.h>
#include <cstdint>
#include <math.h>

#define DEV_INLINE __device__ __forceinline__

// Problem dims (fixed by the dataset)
constexpr int B_ = 128, T_ = 512, F_ = 512, M_ = 512;
constexpr float LN_EPS = 1e-5f;

// GEMM tiling: CTA 256(m) x 128(f) x 32(k); 8 warps of 64x64
constexpr int BM = 256, BN = 128, BK = 32;
constexpr int NKC = T_ / BK;     // 16 k-chunks
constexpr int THREADS = 256;

// Stage sizes in floats
constexpr int A_STAGE = (BM / 16) * 4 * 32 * 4;   // 16 m16-blks * kstep * lane * 4 = 8192
constexpr int B_STAGE = (BN / 8) * 4 * 32 * 2;    // 16 n8-blks  * kstep * lane * 2 = 4096
constexpr int STAGE   = A_STAGE + B_STAGE;        // 12288 floats = 48KB
constexpr int SMEM_BYTES = 2 * STAGE * 4;         // 96KB (dynamic)

// Device scratch (no allocation allowed)
__device__ float g_mean[B_ * F_];
__device__ float g_rstd[B_ * F_];
__device__ float g_Wfrag[M_ * T_];                 // 1MB, frag-order tf32
__device__ float g_Bfrag[(size_t)B_ * T_ * F_];    // 128MB, frag-order tf32

// ---------------- helpers ----------------
DEV_INLINE uint32_t smem_u32(const void* p) {
    uint32_t a;
    asm("{ .reg .u64 t; cvta.to.shared.u64 t, %1; cvt.u32.u64 %0, t; }"
        : "=r"(a) : "l"(p));
    return a;
}

DEV_INLINE float to_tf32(float f) {
    float o;
    asm("cvt.rna.tf32.f32 %0, %1;" : "=f"(o) : "f"(f));
    return o;
}

DEV_INLINE void cp_async16(uint32_t dst_smem, const void* src) {
    asm volatile(
        "{\n\t.reg .u64 g;\n\tcvta.to.global.u64 g, %1;\n\t"
        "cp.async.cg.shared.global [%0], [g], 16;\n\t}"
        :: "r"(dst_smem), "l"(src));
}
DEV_INLINE void cp_commit() { asm volatile("cp.async.commit_group;"); }
template <int N> DEV_INLINE void cp_wait() {
    asm volatile("cp.async.wait_group %0;" :: "n"(N));
}

DEV_INLINE void mma_tf32(float* c, const uint32_t* a, const uint32_t* b) {
    asm volatile(
        "mma.sync.aligned.m16n8k8.row.col.f32.tf32.tf32.f32 "
        "{%0,%1,%2,%3}, {%4,%5,%6,%7}, {%8,%9}, {%0,%1,%2,%3};"
        : "+f"(c[0]), "+f"(c[1]), "+f"(c[2]), "+f"(c[3])
        : "r"(a[0]), "r"(a[1]), "r"(a[2]), "r"(a[3]), "r"(b[0]), "r"(b[1]));
}

DEV_INLINE float gelu_exact(float v) {
    return 0.5f * v * (1.0f + erff(v * 0.70710678118654752f));
}

// ---------------- kernel 1: LN stats over T per (b, f) ----------------
__global__ __launch_bounds__(256) void ln_stats_kernel(const float* __restrict__ x) {
    int b = blockIdx.x >> 1;
    int f = ((blockIdx.x & 1) << 8) + threadIdx.x;
    const float* xp = x + (size_t)b * T_ * F_ + f;
    float s = 0.f, ss = 0.f;
#pragma unroll 8
    for (int t = 0; t < T_; t++) {
        float v = xp[(size_t)t * F_];
        s += v;
        ss += v * v;
    }
    float mean = s * (1.0f / T_);
    float var = ss * (1.0f / T_) - mean * mean;
    g_mean[b * F_ + f] = mean;
    g_rstd[b * F_ + f] = rsqrtf(fmaxf(var, 0.0f) + LN_EPS);
}

// ---------------- kernel 2: pack W into A-fragment order ----------------
// Layout: [m16 (32)][kc (16)][kstep (4)][lane (32)][4]
// lane = g*4+tig; regs: {W[g][tig], W[g+8][tig], W[g][tig+4], W[g+8][tig+4]}
__global__ __launch_bounds__(256) void pack_w_kernel(const float* __restrict__ W) {
    int lin = blockIdx.x * 256 + threadIdx.x;       // 65536 float4s
    int lane = lin & 31;
    int kstep = (lin >> 5) & 3;
    int kc = (lin >> 7) & 15;
    int m16 = lin >> 11;
    int g = lane >> 2, tig = lane & 3;
    int mr = m16 * 16 + g;
    int tc = kc * 32 + kstep * 8 + tig;
    float4 v;
    v.x = to_tf32(W[(size_t)mr * T_ + tc]);
    v.y = to_tf32(W[(size_t)(mr + 8) * T_ + tc]);
    v.z = to_tf32(W[(size_t)mr * T_ + tc + 4]);
    v.w = to_tf32(W[(size_t)(mr + 8) * T_ + tc + 4]);
    reinterpret_cast<float4*>(g_Wfrag)[lin] = v;
}

// ---------------- kernel 3: normalize + transpose x into B-fragment order ----------------
// Layout: [b][ft (4)][kc (16)][n8 (16)][kstep (4)][lane (32)][2]
// lane = g*4+tig; regs: {xn[t=8k+tig][f=8n8+g], xn[t=8k+tig+4][f]}
__global__ __launch_bounds__(256) void pack_xn_kernel(const float* __restrict__ x,
                                                      const float* __restrict__ gamma,
                                                      const float* __restrict__ beta) {
    __shared__ float s[32][132];   // [t_local][f_local], padded
    const int kc = blockIdx.x, ft = blockIdx.y, b = blockIdx.z;
    const int tid = threadIdx.x;

    // load + normalize (coalesced over f)
#pragma unroll
    for (int r = 0; r < 4; r++) {
        int i4 = tid + r * 256;
        int tl = i4 >> 5;
        int f4 = (i4 & 31) << 2;
        int gt = kc * 32 + tl;
        int gf = ft * 128 + f4;
        float4 v = *reinterpret_cast<const float4*>(x + ((size_t)b * T_ + gt) * F_ + gf);
        float4 mu = *reinterpret_cast<const float4*>(g_mean + b * F_ + gf);
        float4 rs = *reinterpret_cast<const float4*>(g_rstd + b * F_ + gf);
        float ga = gamma[gt], be = beta[gt];
        s[tl][f4 + 0] = to_tf32((v.x - mu.x) * rs.x * ga + be);
        s[tl][f4 + 1] = to_tf32((v.y - mu.y) * rs.y * ga + be);
        s[tl][f4 + 2] = to_tf32((v.z - mu.z) * rs.z * ga + be);
        s[tl][f4 + 3] = to_tf32((v.w - mu.w) * rs.w * ga + be);
    }
    __syncthreads();

    // write frag order (coalesced)
    float* dst = g_Bfrag + (((size_t)b * 4 + ft) * 16 + kc) * 4096;
#pragma unroll
    for (int r = 0; r < 4; r++) {
        int o4 = tid + r * 256;                 // 1024 float4s
        int n8 = o4 >> 6;
        int rem = o4 & 63;
        int kstep = rem >> 4;
        int lane0 = (rem & 15) * 2;             // even lane; lane1 = lane0+1
        int g = lane0 >> 2;
        int tig0 = lane0 & 3;
        int t0 = kstep * 8 + tig0;
        int fl = n8 * 8 + g;
        float4 v;
        v.x = s[t0][fl];            // (lane0, h=0)
        v.y = s[t0 + 4][fl];        // (lane0, h=1)
        v.z = s[t0 + 1][fl];        // (lane1, h=0)
        v.w = s[t0 + 5][fl];        // (lane1, h=1)
        reinterpret_cast<float4*>(dst)[o4] = v;
    }
}

// ---------------- kernel 4: tf32 GEMM + bias + GELU + residual ----------------
__global__ __launch_bounds__(THREADS, 1)
void timemix_gemm_kernel(const float* __restrict__ x,
                         const float* __restrict__ bvec,
                         float* __restrict__ out) {
    extern __shared__ float smem[];
    const int tid = threadIdx.x;
    const int wid = tid >> 5, lane = tid & 31;
    const int wm = wid & 3, wn = wid >> 2;          // 4 x 2 warp grid
    const int bm = blockIdx.x;                      // 0..1 (m tiles)
    const int ft = blockIdx.y;                      // 0..3 (f tiles)
    const int b = blockIdx.z;

    const uint32_t smem_base = smem_u32(smem);
    const float* Bsrc_base = g_Bfrag + (((size_t)b * 4 + ft) * 16) * 4096;

    // stage loader
    auto load_stage = [&](int kc, int stg) {
        uint32_t sA = smem_base + stg * (STAGE * 4);
        uint32_t sB = sA + A_STAGE * 4;
        // A: 16 m16-blocks, 2KB each
#pragma unroll
        for (int r = 0; r < 8; r++) {
            int i = tid + r * 256;                  // 2048 float4s
            int m16l = i >> 7;
            int off = i & 127;
            const float* src = g_Wfrag + ((size_t)(bm * 16 + m16l) * 16 + kc) * 512 + off * 4;
            cp_async16(sA + (m16l * 512 + off * 4) * 4, src);
        }
        // B: 16KB contiguous
        const float* Bsrc = Bsrc_base + (size_t)kc * 4096;
#pragma unroll
        for (int r = 0; r < 4; r++) {
            int i = tid + r * 256;                  // 1024 float4s
            cp_async16(sB + i * 16, Bsrc + i * 4);
        }
        cp_commit();
    };

    float acc[4][8][4];
#pragma unroll
    for (int i = 0; i < 4; i++)
#pragma unroll
        for (int j = 0; j < 8; j++)
#pragma unroll
            for (int r = 0; r < 4; r++) acc[i][j][r] = 0.0f;

    load_stage(0, 0);

    for (int kc = 0; kc < NKC; kc++) {
        if (kc + 1 < NKC) {
            load_stage(kc + 1, (kc + 1) & 1);
            cp_wait<1>();
        } else {
            cp_wait<0>();
        }
        __syncthreads();

        const float* sA = smem + (kc & 1) * STAGE;
        const float* sB = sA + A_STAGE;

#pragma unroll
        for (int kstep = 0; kstep < 4; kstep++) {
            uint32_t a[4][4];
#pragma unroll
            for (int i = 0; i < 4; i++) {
                float4 v = *reinterpret_cast<const float4*>(
                    sA + ((wm * 4 + i) * 4 + kstep) * 128 + lane * 4);
                a[i][0] = __float_as_uint(v.x);
                a[i][1] = __float_as_uint(v.y);
                a[i][2] = __float_as_uint(v.z);
                a[i][3] = __float_as_uint(v.w);
            }
            uint32_t bfr[8][2];
#pragma unroll
            for (int j = 0; j < 8; j++) {
                float2 v = *reinterpret_cast<const float2*>(
                    sB + ((wn * 8 + j) * 4 + kstep) * 64 + lane * 2);
                bfr[j][0] = __float_as_uint(v.x);
                bfr[j][1] = __float_as_uint(v.y);
            }
#pragma unroll
            for (int i = 0; i < 4; i++)
#pragma unroll
                for (int j = 0; j < 8; j++)
                    mma_tf32(acc[i][j], a[i], bfr[j]);
        }
        __syncthreads();
    }

    // ---- epilogue: bias + exact GELU + residual ----
    const int g = lane >> 2, tig = lane & 3;
    const int m_warp = bm * 256 + wm * 64;
    const int f_warp = ft * 128 + wn * 64;
#pragma unroll
    for (int i = 0; i < 4; i++) {
#pragma unroll
        for (int h = 0; h < 2; h++) {
            int m = m_warp + i * 16 + g + 8 * h;
            float bv = bvec[m];
            const float* xr = x + ((size_t)b * M_ + m) * F_ + f_warp;
            float* yr = out + ((size_t)b * M_ + m) * F_ + f_warp;
#pragma unroll
            for (int j = 0; j < 8; j++) {
                int fo = j * 8 + tig * 2;
                float2 xv = *reinterpret_cast<const float2*>(xr + fo);
                float c0 = acc[i][j][2 * h + 0];
                float c1 = acc[i][j][2 * h + 1];
                float2 o;
                o.x = gelu_exact(c0 + bv) + xv.x;
                o.y = gelu_exact(c1 + bv) + xv.y;
                *reinterpret_cast<float2*>(yr + fo) = o;
            }
        }
    }
}

// ---------------- launch ----------------
extern "C" void kernel_launch(void* const* d_in, const int* in_sizes, int n_in,
                              void* d_out, int out_size) {
    const float* x     = (const float*)d_in[0];
    const float* gamma = (const float*)d_in[1];
    const float* beta  = (const float*)d_in[2];
    const float* W     = (const float*)d_in[3];
    const float* bvec  = (const float*)d_in[4];
    float* out = (float*)d_out;

    cudaFuncSetAttribute(timemix_gemm_kernel,
                         cudaFuncAttributeMaxDynamicSharedMemorySize, SMEM_BYTES);

    ln_stats_kernel<<<(B_ * F_) / 256, 256>>>(x);
    pack_w_kernel<<<(M_ * T_ / 4) / 256, 256>>>(W);
    {
        dim3 grid(NKC, F_ / 128, B_);
        pack_xn_kernel<<<grid, 256>>>(x, gamma, beta);
    }
    {
        dim3 grid(M_ / BM, F_ / BN, B_);   // (2, 4, 128)
        timemix_gemm_kernel<<<grid, THREADS, SMEM_BYTES>>>(x, bvec, out);
    }
}